// round 3
// baseline (speedup 1.0000x reference)
#include <cuda_runtime.h>
#include <cuda_fp16.h>
#include <cstdint>
#include <cstddef>

#define N_NODE 100000
#define NTOT   102000
#define NFEAT  256
#define NDIM   128

// fp16 mirror of x1 for low-traffic SpMM gathers (26.1 MB, L2-resident).
__device__ __half2 g_x1h[(size_t)NTOT * (NDIM / 2)];

// ---------------------------------------------------------------------------
// GEMM: x1[NTOT,128] = concat(emb_node, emb_attri)[NTOT,256] @ W1[128,256]^T
// 128x128 tile, BK=32, 256 threads, 8x8 microtile, float4 LDS compute reads.
// Epilogue writes fp32 x1 (output) AND fp16 mirror (SpMM gather source).
// ---------------------------------------------------------------------------
__global__ __launch_bounds__(256, 2) void gemm_x1_kernel(
    const float* __restrict__ emb_node,
    const float* __restrict__ emb_attri,
    const float* __restrict__ W1,
    float* __restrict__ x1)
{
    // 132-float rows: 528B, 16B-aligned -> LDS.128-friendly, conflict-padded.
    __shared__ float As[32][132];   // [k][m]
    __shared__ float Bs[32][132];   // [k][n]

    const int tid = threadIdx.x;
    const int m0  = blockIdx.x * 128;
    const int tr  = tid >> 4;   // 0..15
    const int tc  = tid & 15;   // 0..15

    float acc[8][8];
#pragma unroll
    for (int i = 0; i < 8; i++)
#pragma unroll
        for (int j = 0; j < 8; j++) acc[i][j] = 0.f;

    for (int k0 = 0; k0 < NFEAT; k0 += 32) {
#pragma unroll
        for (int i = 0; i < 4; i++) {
            int idx = tid + i * 256;       // 1024 float4 slots
            int r   = idx >> 3;
            int c4  = idx & 7;
            int gr  = m0 + r;
            float4 v = make_float4(0.f, 0.f, 0.f, 0.f);
            if (gr < NTOT) {
                const float* src = (gr < N_NODE)
                    ? (emb_node + (size_t)gr * NFEAT)
                    : (emb_attri + (size_t)(gr - N_NODE) * NFEAT);
                v = __ldg((const float4*)(src + k0) + c4);
            }
            As[c4 * 4 + 0][r] = v.x;
            As[c4 * 4 + 1][r] = v.y;
            As[c4 * 4 + 2][r] = v.z;
            As[c4 * 4 + 3][r] = v.w;
        }
#pragma unroll
        for (int i = 0; i < 4; i++) {
            int idx = tid + i * 256;
            int j   = idx >> 3;
            int c4  = idx & 7;
            float4 v = __ldg((const float4*)(W1 + (size_t)j * NFEAT + k0) + c4);
            Bs[c4 * 4 + 0][j] = v.x;
            Bs[c4 * 4 + 1][j] = v.y;
            Bs[c4 * 4 + 2][j] = v.z;
            Bs[c4 * 4 + 3][j] = v.w;
        }
        __syncthreads();

#pragma unroll
        for (int kk = 0; kk < 32; kk++) {
            float4 a0 = *(const float4*)&As[kk][tr * 8];
            float4 a1 = *(const float4*)&As[kk][tr * 8 + 4];
            float4 b0 = *(const float4*)&Bs[kk][tc * 8];
            float4 b1 = *(const float4*)&Bs[kk][tc * 8 + 4];
            float ra[8] = {a0.x, a0.y, a0.z, a0.w, a1.x, a1.y, a1.z, a1.w};
            float rb[8] = {b0.x, b0.y, b0.z, b0.w, b1.x, b1.y, b1.z, b1.w};
#pragma unroll
            for (int i = 0; i < 8; i++)
#pragma unroll
                for (int j = 0; j < 8; j++)
                    acc[i][j] = fmaf(ra[i], rb[j], acc[i][j]);
        }
        __syncthreads();
    }

#pragma unroll
    for (int i = 0; i < 8; i++) {
        int gr = m0 + tr * 8 + i;
        if (gr < NTOT) {
            float4* dst = (float4*)(x1 + (size_t)gr * NDIM + tc * 8);
            dst[0] = make_float4(acc[i][0], acc[i][1], acc[i][2], acc[i][3]);
            dst[1] = make_float4(acc[i][4], acc[i][5], acc[i][6], acc[i][7]);
            // fp16 mirror: 8 floats -> 4 half2 = one 16-byte store
            __half2 h[4];
            h[0] = __float22half2_rn(make_float2(acc[i][0], acc[i][1]));
            h[1] = __float22half2_rn(make_float2(acc[i][2], acc[i][3]));
            h[2] = __float22half2_rn(make_float2(acc[i][4], acc[i][5]));
            h[3] = __float22half2_rn(make_float2(acc[i][6], acc[i][7]));
            uint4 packed = *(uint4*)h;   // 4 x half2 = 16 bytes
            *(uint4*)(&g_x1h[(size_t)gr * (NDIM / 2) + tc * 4]) = packed;
        }
    }
}

// ---------------------------------------------------------------------------
// SpMM scatter: out[row[e], :] += val[e] * x1[col[e], :]
// One warp per edge. Gather fp16 (256B/row, half the traffic), exact fp32
// red.global.add.v4 scatter.
// ---------------------------------------------------------------------------
__global__ __launch_bounds__(256) void spmm_kernel(
    const int*   __restrict__ row,
    const int*   __restrict__ col,
    const float* __restrict__ val,
    float*       __restrict__ out,
    int nedges)
{
    const int warp = (int)((blockIdx.x * (unsigned)blockDim.x + threadIdx.x) >> 5);
    const int lane = threadIdx.x & 31;
    if (warp >= nedges) return;

    const int   r = __ldg(row + warp);
    const int   c = __ldg(col + warp);
    const float v = __ldg(val + warp);

    // lane handles floats [4*lane, 4*lane+4) -> 2 half2 = 8 bytes
    float2 raw = __ldg((const float2*)(g_x1h + (size_t)c * (NDIM / 2)) + lane);
    __half2 h0 = *(__half2*)&raw.x;
    __half2 h1 = *(__half2*)&raw.y;
    float2 f0 = __half22float2(h0);
    float2 f1 = __half22float2(h1);

    float4 y;
    y.x = f0.x * v; y.y = f0.y * v; y.z = f1.x * v; y.w = f1.y * v;

    float* dst = out + (size_t)r * NDIM + lane * 4;
    asm volatile("red.global.add.v4.f32 [%0], {%1, %2, %3, %4};"
                 :: "l"(dst), "f"(y.x), "f"(y.y), "f"(y.z), "f"(y.w)
                 : "memory");
}

// ---------------------------------------------------------------------------
// Launch
// ---------------------------------------------------------------------------
extern "C" void kernel_launch(void* const* d_in, const int* in_sizes, int n_in,
                              void* d_out, int out_size)
{
    const float* emb_node  = (const float*)d_in[0];
    const float* emb_attri = (const float*)d_in[1];
    const float* W1        = (const float*)d_in[2];
    const int*   adj_row   = (const int*)d_in[3];
    const int*   adj_col   = (const int*)d_in[4];
    const float* adj_val   = (const float*)d_in[5];
    const int*   adj2_row  = (const int*)d_in[6];
    const int*   adj2_col  = (const int*)d_in[7];
    const float* adj2_val  = (const float*)d_in[8];

    const int E1 = in_sizes[3];
    const int E2 = in_sizes[6];

    float* out = (float*)d_out;
    float* x1 = out;
    float* x2 = out + (size_t)NTOT * NDIM;
    float* x3 = out + (size_t)2 * NTOT * NDIM;

    cudaMemsetAsync(x2, 0, (size_t)2 * NTOT * NDIM * sizeof(float));

    int gemm_blocks = (NTOT + 127) / 128;
    gemm_x1_kernel<<<gemm_blocks, 256>>>(emb_node, emb_attri, W1, x1);

    int blocks1 = (int)(((long long)E1 * 32 + 255) / 256);
    int blocks2 = (int)(((long long)E2 * 32 + 255) / 256);
    spmm_kernel<<<blocks1, 256>>>(adj_row, adj_col, adj_val, x2, E1);
    spmm_kernel<<<blocks2, 256>>>(adj2_row, adj2_col, adj2_val, x3, E2);
}

// round 5
// speedup vs baseline: 1.1501x; 1.1501x over previous
#include <cuda_runtime.h>
#include <cuda_fp16.h>
#include <cstdint>
#include <cstddef>

#define N_NODE 100000
#define NTOT   102000
#define NFEAT  256
#define NDIM   128
#define EMAX   1700000

// fp16 mirror of x1 for low-traffic SpMM gathers (26.1 MB, L2-resident).
__device__ __half2 g_x1h[(size_t)NTOT * (NDIM / 2)];

// CSR scratch (built per call; no device mallocs allowed).
__device__ int   g_cnt[2][NTOT];
__device__ int   g_off[2][NTOT + 1];
__device__ int   g_cur[2][NTOT];
__device__ int   g_scol[2][EMAX];
__device__ float g_sval[2][EMAX];

// ---------------------------------------------------------------------------
// GEMM: x1 = concat(emb) @ W1^T using packed fma.rn.f32x2 (FFMA2).
// 128x128 tile, BK=32, 256 threads, 8x8 microtile (as 8x4 f32x2 pairs).
// ---------------------------------------------------------------------------
__global__ __launch_bounds__(256, 2) void gemm_x1_kernel(
    const float* __restrict__ emb_node,
    const float* __restrict__ emb_attri,
    const float* __restrict__ W1,
    float* __restrict__ x1)
{
    __shared__ float As[32][132];
    __shared__ float Bs[32][132];

    const int tid = threadIdx.x;
    const int m0  = blockIdx.x * 128;
    const int tr  = tid >> 4;
    const int tc  = tid & 15;

    unsigned long long acc2[8][4];   // 8 rows x 4 f32x2 column-pairs
#pragma unroll
    for (int i = 0; i < 8; i++)
#pragma unroll
        for (int j = 0; j < 4; j++) acc2[i][j] = 0ULL;

    for (int k0 = 0; k0 < NFEAT; k0 += 32) {
#pragma unroll
        for (int i = 0; i < 4; i++) {
            int idx = tid + i * 256;
            int r   = idx >> 3;
            int c4  = idx & 7;
            int gr  = m0 + r;
            float4 v = make_float4(0.f, 0.f, 0.f, 0.f);
            if (gr < NTOT) {
                const float* src = (gr < N_NODE)
                    ? (emb_node + (size_t)gr * NFEAT)
                    : (emb_attri + (size_t)(gr - N_NODE) * NFEAT);
                v = __ldg((const float4*)(src + k0) + c4);
            }
            As[c4 * 4 + 0][r] = v.x;
            As[c4 * 4 + 1][r] = v.y;
            As[c4 * 4 + 2][r] = v.z;
            As[c4 * 4 + 3][r] = v.w;
        }
#pragma unroll
        for (int i = 0; i < 4; i++) {
            int idx = tid + i * 256;
            int j   = idx >> 3;
            int c4  = idx & 7;
            float4 v = __ldg((const float4*)(W1 + (size_t)j * NFEAT + k0) + c4);
            Bs[c4 * 4 + 0][j] = v.x;
            Bs[c4 * 4 + 1][j] = v.y;
            Bs[c4 * 4 + 2][j] = v.z;
            Bs[c4 * 4 + 3][j] = v.w;
        }
        __syncthreads();

#pragma unroll
        for (int kk = 0; kk < 32; kk++) {
            float4 a0 = *(const float4*)&As[kk][tr * 8];
            float4 a1 = *(const float4*)&As[kk][tr * 8 + 4];
            float4 b0 = *(const float4*)&Bs[kk][tc * 8];
            float4 b1 = *(const float4*)&Bs[kk][tc * 8 + 4];
            float ra[8] = {a0.x, a0.y, a0.z, a0.w, a1.x, a1.y, a1.z, a1.w};
            float rb[8] = {b0.x, b0.y, b0.z, b0.w, b1.x, b1.y, b1.z, b1.w};

            unsigned long long ra2[8], rb2[4];
#pragma unroll
            for (int i = 0; i < 8; i++)
                asm("mov.b64 %0, {%1, %2};" : "=l"(ra2[i]) : "f"(ra[i]), "f"(ra[i]));
#pragma unroll
            for (int j = 0; j < 4; j++)
                asm("mov.b64 %0, {%1, %2};" : "=l"(rb2[j]) : "f"(rb[2 * j]), "f"(rb[2 * j + 1]));
#pragma unroll
            for (int i = 0; i < 8; i++)
#pragma unroll
                for (int j = 0; j < 4; j++)
                    asm("fma.rn.f32x2 %0, %1, %2, %0;"
                        : "+l"(acc2[i][j]) : "l"(ra2[i]), "l"(rb2[j]));
        }
        __syncthreads();
    }

#pragma unroll
    for (int i = 0; i < 8; i++) {
        int gr = m0 + tr * 8 + i;
        if (gr < NTOT) {
            float o[8];
#pragma unroll
            for (int j = 0; j < 4; j++)
                asm("mov.b64 {%0, %1}, %2;"
                    : "=f"(o[2 * j]), "=f"(o[2 * j + 1]) : "l"(acc2[i][j]));
            float4* dst = (float4*)(x1 + (size_t)gr * NDIM + tc * 8);
            dst[0] = make_float4(o[0], o[1], o[2], o[3]);
            dst[1] = make_float4(o[4], o[5], o[6], o[7]);
            __half2 h[4];
            h[0] = __float22half2_rn(make_float2(o[0], o[1]));
            h[1] = __float22half2_rn(make_float2(o[2], o[3]));
            h[2] = __float22half2_rn(make_float2(o[4], o[5]));
            h[3] = __float22half2_rn(make_float2(o[6], o[7]));
            *(uint4*)(&g_x1h[(size_t)gr * (NDIM / 2) + tc * 4]) = *(uint4*)h;
        }
    }
}

// ---------------------------------------------------------------------------
// CSR build: zero counts -> histogram -> scan -> reorder
// ---------------------------------------------------------------------------
__global__ void zero_cnt_kernel()
{
    int i = blockIdx.x * blockDim.x + threadIdx.x;
    if (i < 2 * NTOT) ((int*)g_cnt)[i] = 0;
}

__global__ void hist_kernel(const int* __restrict__ row, int E, int which)
{
    int i = blockIdx.x * blockDim.x + threadIdx.x;
    if (i < E) atomicAdd(&g_cnt[which][__ldg(row + i)], 1);
}

__global__ void scan_kernel()   // <<<2, 1024>>>, blockIdx.x = adjacency
{
    const int which = blockIdx.x;
    const int CH = 100;          // 1024*100 = 102400 >= NTOT
    __shared__ int part[1024];
    int t = threadIdx.x;
    int base = t * CH;
    int s = 0;
    for (int k = 0; k < CH; k++) {
        int idx = base + k;
        if (idx < NTOT) s += g_cnt[which][idx];
    }
    part[t] = s;
    __syncthreads();
    for (int off = 1; off < 1024; off <<= 1) {
        int v = (t >= off) ? part[t - off] : 0;
        __syncthreads();
        part[t] += v;
        __syncthreads();
    }
    int run = part[t] - s;       // exclusive prefix of this chunk
    for (int k = 0; k < CH; k++) {
        int idx = base + k;
        if (idx < NTOT) {
            g_off[which][idx] = run;
            g_cur[which][idx] = run;
            run += g_cnt[which][idx];
        }
    }
    if (t == 1023) g_off[which][NTOT] = run;
}

__global__ void reorder_kernel(const int* __restrict__ row,
                               const int* __restrict__ col,
                               const float* __restrict__ val,
                               int E, int which)
{
    int i = blockIdx.x * blockDim.x + threadIdx.x;
    if (i >= E) return;
    int r = __ldg(row + i);
    int pos = atomicAdd(&g_cur[which][r], 1);
    g_scol[which][pos] = __ldg(col + i);
    g_sval[which][pos] = __ldg(val + i);
}

// ---------------------------------------------------------------------------
// CSR SpMM: one warp per output row, register accumulation, single store.
// ---------------------------------------------------------------------------
__global__ __launch_bounds__(256) void spmm_csr_kernel(
    float* __restrict__ out, int which)
{
    const int w    = (int)((blockIdx.x * (unsigned)blockDim.x + threadIdx.x) >> 5);
    const int lane = threadIdx.x & 31;
    if (w >= NTOT) return;

    const int s = g_off[which][w];
    const int e = g_off[which][w + 1];
    const int*   scol = g_scol[which];
    const float* sval = g_sval[which];

    float4 acc = make_float4(0.f, 0.f, 0.f, 0.f);

    int i = s;
    for (; i + 1 < e; i += 2) {
        int   c0 = __ldg(scol + i);
        int   c1 = __ldg(scol + i + 1);
        float v0 = __ldg(sval + i);
        float v1 = __ldg(sval + i + 1);
        float2 r0 = __ldg((const float2*)(g_x1h + (size_t)c0 * (NDIM / 2)) + lane);
        float2 r1 = __ldg((const float2*)(g_x1h + (size_t)c1 * (NDIM / 2)) + lane);
        float2 a0 = __half22float2(*(__half2*)&r0.x);
        float2 b0 = __half22float2(*(__half2*)&r0.y);
        float2 a1 = __half22float2(*(__half2*)&r1.x);
        float2 b1 = __half22float2(*(__half2*)&r1.y);
        acc.x = fmaf(a0.x, v0, acc.x); acc.y = fmaf(a0.y, v0, acc.y);
        acc.z = fmaf(b0.x, v0, acc.z); acc.w = fmaf(b0.y, v0, acc.w);
        acc.x = fmaf(a1.x, v1, acc.x); acc.y = fmaf(a1.y, v1, acc.y);
        acc.z = fmaf(b1.x, v1, acc.z); acc.w = fmaf(b1.y, v1, acc.w);
    }
    if (i < e) {
        int   c0 = __ldg(scol + i);
        float v0 = __ldg(sval + i);
        float2 r0 = __ldg((const float2*)(g_x1h + (size_t)c0 * (NDIM / 2)) + lane);
        float2 a0 = __half22float2(*(__half2*)&r0.x);
        float2 b0 = __half22float2(*(__half2*)&r0.y);
        acc.x = fmaf(a0.x, v0, acc.x); acc.y = fmaf(a0.y, v0, acc.y);
        acc.z = fmaf(b0.x, v0, acc.z); acc.w = fmaf(b0.y, v0, acc.w);
    }

    *((float4*)(out + (size_t)w * NDIM) + lane) = acc;
}

// ---------------------------------------------------------------------------
// Launch
// ---------------------------------------------------------------------------
extern "C" void kernel_launch(void* const* d_in, const int* in_sizes, int n_in,
                              void* d_out, int out_size)
{
    const float* emb_node  = (const float*)d_in[0];
    const float* emb_attri = (const float*)d_in[1];
    const float* W1        = (const float*)d_in[2];
    const int*   adj_row   = (const int*)d_in[3];
    const int*   adj_col   = (const int*)d_in[4];
    const float* adj_val   = (const float*)d_in[5];
    const int*   adj2_row  = (const int*)d_in[6];
    const int*   adj2_col  = (const int*)d_in[7];
    const float* adj2_val  = (const float*)d_in[8];

    const int E1 = in_sizes[3];
    const int E2 = in_sizes[6];

    float* out = (float*)d_out;
    float* x1 = out;
    float* x2 = out + (size_t)NTOT * NDIM;
    float* x3 = out + (size_t)2 * NTOT * NDIM;

    // CSR build for both adjacencies
    zero_cnt_kernel<<<(2 * NTOT + 255) / 256, 256>>>();
    hist_kernel<<<(E1 + 255) / 256, 256>>>(adj_row, E1, 0);
    hist_kernel<<<(E2 + 255) / 256, 256>>>(adj2_row, E2, 1);

    // GEMM (also fills fp16 mirror)
    int gemm_blocks = (NTOT + 127) / 128;
    gemm_x1_kernel<<<gemm_blocks, 256>>>(emb_node, emb_attri, W1, x1);

    scan_kernel<<<2, 1024>>>();
    reorder_kernel<<<(E1 + 255) / 256, 256>>>(adj_row, adj_col, adj_val, E1, 0);
    reorder_kernel<<<(E2 + 255) / 256, 256>>>(adj2_row, adj2_col, adj2_val, E2, 1);

    // Atomic-free segment-reduce SpMMs (write every row -> no memset needed)
    int spmm_blocks = (NTOT * 32 + 255) / 256;
    spmm_csr_kernel<<<spmm_blocks, 256>>>(x2, 0);
    spmm_csr_kernel<<<spmm_blocks, 256>>>(x3, 1);
}